// round 13
// baseline (speedup 1.0000x reference)
#include <cuda_runtime.h>
#include <cuda_fp16.h>
#include <math.h>
#include <stdint.h>

#define N_ENT 100000
#define N_REL 12
#define DD 64
#define NE 1000000
#define OUTD 160   // 64 + 64 + 32
#define NSCAN ((N_ENT + 1023) / 1024)   // 98
#define TILE_M 128
#define NTILES_M ((N_ENT + TILE_M - 1) / TILE_M)   // 782
#define PITCH 72   // fp32 smem pitch for mlp0 (unchanged, validated)
#define AP 80      // fp16 smem pitch: 40 words == 8 mod 32 -> conflict-free LDS.64

// ---------------- device scratch (no allocations allowed) ----------------
__device__ __half g_proj[(size_t)N_ENT * N_REL * DD];  // 153.6 MB (fp16)
__device__ __half g_embh[(size_t)N_ENT * DD];          // fp16 emb copy
__device__ __half g_x1h[(size_t)N_ENT * DD];           // fp16 x1 copy (aligned)
__device__ __half g_Wth[N_REL * DD * DD];  // W_r^T fp16, fragment-permuted (perm16)
__device__ float g_Wm[2 * DD * DD];        // W1_0^T, W2_0^T permuted tf32
__device__ float g_logits[NE];             // logits in CSR (dst-sorted) order
__device__ float g_attp[NE];               // att in CSR order
__device__ int4  g_edge[NE];               // CSR slot -> (src, etype, dst, _)
__device__ int   g_cnt[N_ENT];
__device__ int   g_off[N_ENT + 1];
__device__ int   g_cursor[N_ENT];
__device__ int   g_bsum[NSCAN];
__device__ float g_hn0[(size_t)N_ENT * DD];
__device__ float g_hn1[(size_t)N_ENT * DD];

// ---------------- helpers ----------------
__device__ __forceinline__ float leaky(float x) { return x > 0.0f ? x : 0.01f * x; }
__device__ __forceinline__ void fma4(float4& a, float s, float4 w) {
    a.x += s * w.x; a.y += s * w.y; a.z += s * w.z; a.w += s * w.w;
}
__device__ __forceinline__ float to_tf32(float v) {
    float r;
    asm("cvt.rna.tf32.f32 %0, %1;" : "=f"(r) : "f"(v));
    return r;
}
__device__ __forceinline__ float ftanh(float x) {
    x = fminf(fmaxf(x, -20.f), 20.f);
    float e = __expf(2.f * x);
    return (e - 1.f) / (e + 1.f);
}
// perm16: within each 16-half group, thread t4's m16n8k16 fragment halves
// {2t4, 2t4+1, 8+2t4, 8+2t4+1} become 4 contiguous halves at 4*t4.
__device__ __forceinline__ int perm16(int k) {
    return (k & ~15) + (((k & 7) >> 1) << 2) + (((k & 8) >> 3) << 1) + (k & 1);
}
// m16n8k8 tf32 (mlp0)
__device__ __forceinline__ void mma_tf32(float c[4], uint32_t a0, uint32_t a1,
                                         uint32_t a2, uint32_t a3,
                                         uint32_t b0, uint32_t b1) {
    asm volatile(
        "mma.sync.aligned.m16n8k8.row.col.f32.tf32.tf32.f32 "
        "{%0,%1,%2,%3}, {%4,%5,%6,%7}, {%8,%9}, {%0,%1,%2,%3};"
        : "+f"(c[0]), "+f"(c[1]), "+f"(c[2]), "+f"(c[3])
        : "r"(a0), "r"(a1), "r"(a2), "r"(a3), "r"(b0), "r"(b1));
}
// m16n8k16 fp16 in, fp32 accumulate
__device__ __forceinline__ void mma_f16(float c[4], uint32_t a0, uint32_t a1,
                                        uint32_t a2, uint32_t a3,
                                        uint32_t b0, uint32_t b1) {
    asm volatile(
        "mma.sync.aligned.m16n8k16.row.col.f32.f16.f16.f32 "
        "{%0,%1,%2,%3}, {%4,%5,%6,%7}, {%8,%9}, {%0,%1,%2,%3};"
        : "+f"(c[0]), "+f"(c[1]), "+f"(c[2]), "+f"(c[3])
        : "r"(a0), "r"(a1), "r"(a2), "r"(a3), "r"(b0), "r"(b1));
}

// ---------------- CSR build ----------------
__global__ void k_init() {
    int i = blockIdx.x * blockDim.x + threadIdx.x;
    if (i < N_ENT) g_cnt[i] = 0;
}

__global__ void k_hist(const int* __restrict__ dst) {
    int e = blockIdx.x * 256 + threadIdx.x;
    if (e < NE) atomicAdd(&g_cnt[dst[e]], 1);
}

__global__ void k_scan1() {
    __shared__ int s[1024];
    int i = blockIdx.x * 1024 + threadIdx.x;
    int v = (i < N_ENT) ? g_cnt[i] : 0;
    s[threadIdx.x] = v;
    __syncthreads();
    for (int off = 1; off < 1024; off <<= 1) {
        int t = (threadIdx.x >= off) ? s[threadIdx.x - off] : 0;
        __syncthreads();
        s[threadIdx.x] += t;
        __syncthreads();
    }
    if (i < N_ENT) g_off[i] = s[threadIdx.x] - v;
    if (threadIdx.x == 1023) g_bsum[blockIdx.x] = s[1023];
}

__global__ void k_scan2() {
    __shared__ int s[128];
    int t = threadIdx.x;
    int v0 = (t < NSCAN) ? g_bsum[t] : 0;
    s[t] = v0;
    __syncthreads();
    for (int off = 1; off < 128; off <<= 1) {
        int v = (t >= off) ? s[t - off] : 0;
        __syncthreads();
        s[t] += v;
        __syncthreads();
    }
    if (t < NSCAN) g_bsum[t] = s[t] - v0;   // exclusive
}

__global__ void k_scan3() {
    int i = blockIdx.x * 256 + threadIdx.x;
    if (i < N_ENT) {
        int o = g_off[i] + g_bsum[i >> 10];
        g_off[i] = o;
        g_cursor[i] = o;
    }
    if (i == 0) g_off[N_ENT] = NE;
}

__global__ void k_fill(const int* __restrict__ src, const int* __restrict__ dst,
                       const int* __restrict__ et) {
    int e = blockIdx.x * 256 + threadIdx.x;
    if (e < NE) {
        int d = dst[e];
        int pos = atomicAdd(&g_cursor[d], 1);
        g_edge[pos] = make_int4(src[e], et[e], d, 0);
    }
}

// ---------------- preps ----------------
// W_r^T fp16 with perm16 on the k (=d) index: g_Wth[r][j][perm16(d)] = W[r][d][j]
__global__ void k_prepW(const float* __restrict__ Wr) {
    int idx = blockIdx.x * 256 + threadIdx.x;
    if (idx >= N_REL * DD * DD) return;
    int r = idx >> 12;
    int e = idx & 4095;
    int d = e >> 6, j = e & 63;
    g_Wth[r * 4096 + j * DD + perm16(d)] = __float2half(Wr[idx]);
}

__global__ void k_prepWm(const float* __restrict__ W1, const float* __restrict__ W2) {
    int idx = blockIdx.x * 256 + threadIdx.x;
    if (idx >= 2 * DD * DD) return;
    const float* srcw = (idx < 4096) ? W1 : W2;
    int e = idx & 4095;
    int j = e >> 6, d = e & 63;
    int pd = (d >> 3) * 8 + (d & 3) * 2 + ((d & 7) >> 2);
    g_Wm[(idx >> 12) * 4096 + j * DD + pd] = to_tf32(srcw[e]);
}

__global__ void k_embh(const float* __restrict__ emb) {
    int i = blockIdx.x * 256 + threadIdx.x;
    if (i < N_ENT * DD / 2) {
        float2 v = ((const float2*)emb)[i];
        ((__half2*)g_embh)[i] = __floats2half2_rn(v.x, v.y);
    }
}

// ---------------- fp16 m16n8k16 proj, 4Mx2N warp tiling -------------------
// Warp (wm, wn): rows [wm*32, +32) (two m16 tiles), cols [wn*32, +32) (4 n8).
// A fragments hoisted to regs; B fragments LDG'd directly from L1/L2-resident
// g_Wth. Relation loop: NO smem, NO barriers.
__global__ void k_projmma(const float* __restrict__ emb) {
    extern __shared__ char dsmc[];
    __half* smA = (__half*)dsmc;             // [128][AP], used only for staging
    const int tid = threadIdx.x;
    const int wid = tid >> 5, lane = tid & 31;
    const int g = lane >> 2, t4 = lane & 3;
    const int wm = wid >> 1, wn = wid & 1;
    const int n0 = blockIdx.x * TILE_M;

    // stage A tile (zero-fill OOB), fp16, fragment-permuted
    for (int idx = tid; idx < TILE_M * 16; idx += 256) {
        int m = idx >> 4, c = idx & 15;
        float4 v = make_float4(0.f, 0.f, 0.f, 0.f);
        if (n0 + m < N_ENT) v = ((const float4*)(emb + (size_t)(n0 + m) * DD))[c];
        int k0 = c * 4;
        *(__half2*)&smA[m * AP + perm16(k0)]     = __floats2half2_rn(v.x, v.y);
        *(__half2*)&smA[m * AP + perm16(k0 + 2)] = __floats2half2_rn(v.z, v.w);
    }
    __syncthreads();

    const int mb = wm * 32;
    // hoist A fragments: 2 m-tiles x 4 k16-steps (reused across 12 r)
    uint32_t af[2][4][4];
#pragma unroll
    for (int t = 0; t < 2; t++)
#pragma unroll
        for (int ks = 0; ks < 4; ks++) {
            uint2 ra = *(const uint2*)&smA[(mb + t * 16 + g)     * AP + ks * 16 + t4 * 4];
            uint2 rb = *(const uint2*)&smA[(mb + t * 16 + g + 8) * AP + ks * 16 + t4 * 4];
            af[t][ks][0] = ra.x;
            af[t][ks][1] = rb.x;
            af[t][ks][2] = ra.y;
            af[t][ks][3] = rb.y;
        }

    const __half* __restrict__ wbase = g_Wth + (size_t)wn * 32 * DD;

    for (int r = 0; r < N_REL; r++) {
        const __half* __restrict__ wr = wbase + r * 4096;
        float acc[2][4][4];
#pragma unroll
        for (int t = 0; t < 2; t++)
#pragma unroll
            for (int nt = 0; nt < 4; nt++)
#pragma unroll
                for (int q = 0; q < 4; q++) acc[t][nt][q] = 0.f;

#pragma unroll
        for (int ks = 0; ks < 4; ks++) {
#pragma unroll
            for (int nt = 0; nt < 4; nt++) {
                uint2 b = *(const uint2*)&wr[(nt * 8 + g) * DD + ks * 16 + t4 * 4];
                mma_f16(acc[0][nt], af[0][ks][0], af[0][ks][1], af[0][ks][2], af[0][ks][3], b.x, b.y);
                mma_f16(acc[1][nt], af[1][ks][0], af[1][ks][1], af[1][ks][2], af[1][ks][3], b.x, b.y);
            }
        }

#pragma unroll
        for (int t = 0; t < 2; t++) {
            int row0 = n0 + mb + t * 16 + g;
            int row1 = row0 + 8;
            if (row0 < N_ENT) {
                __half2* base = (__half2*)(g_proj + ((size_t)row0 * N_REL + r) * DD + wn * 32);
#pragma unroll
                for (int nt = 0; nt < 4; nt++)
                    base[nt * 4 + t4] = __floats2half2_rn(acc[t][nt][0], acc[t][nt][1]);
            }
            if (row1 < N_ENT) {
                __half2* base = (__half2*)(g_proj + ((size_t)row1 * N_REL + r) * DD + wn * 32);
#pragma unroll
                for (int nt = 0; nt < 4; nt++)
                    base[nt * 4 + t4] = __floats2half2_rn(acc[t][nt][2], acc[t][nt][3]);
            }
        }
    }
}

// ---------------- per-edge logits, 2 edges per warp (MLP=2) --------------
__global__ void k_logits(const float* __restrict__ rel_emb) {
    int q = blockIdx.x * 8 + (threadIdx.x >> 5);
    int p0 = q * 2;
    if (p0 >= NE) return;
    int l = threadIdx.x & 31;
    int4 e0 = g_edge[p0];
    int4 e1 = g_edge[p0 + 1];

    const __half2* pt0 = (const __half2*)(g_proj + ((size_t)e0.x * N_REL + e0.y) * DD);
    const __half2* pt1 = (const __half2*)(g_proj + ((size_t)e1.x * N_REL + e1.y) * DD);
    const __half2* ph0 = (const __half2*)(g_proj + ((size_t)e0.z * N_REL + e0.y) * DD);
    const __half2* ph1 = (const __half2*)(g_proj + ((size_t)e1.z * N_REL + e1.y) * DD);
    __half2 tv0h = pt0[l], tv1h = pt1[l];
    __half2 hv0h = ph0[l], hv1h = ph1[l];
    float2 rr0 = ((const float2*)(rel_emb + (size_t)e0.y * DD))[l];
    float2 rr1 = ((const float2*)(rel_emb + (size_t)e1.y * DD))[l];

    float2 tv0 = __half22float2(tv0h), hv0 = __half22float2(hv0h);
    float2 tv1 = __half22float2(tv1h), hv1 = __half22float2(hv1h);

    float s0 = tv0.x * ftanh(hv0.x + rr0.x) + tv0.y * ftanh(hv0.y + rr0.y);
    float s1 = tv1.x * ftanh(hv1.x + rr1.x) + tv1.y * ftanh(hv1.y + rr1.y);
#pragma unroll
    for (int o = 16; o; o >>= 1) {
        s0 += __shfl_xor_sync(0xffffffffu, s0, o);
        s1 += __shfl_xor_sync(0xffffffffu, s1, o);
    }
    if (l == 0) *(float2*)&g_logits[p0] = make_float2(s0, s1);
}

// ---------------- fused softmax + layer-0 gather (warp per node) ----------
__global__ void k_attgather() {
    int n = blockIdx.x * 8 + (threadIdx.x >> 5);
    if (n >= N_ENT) return;
    int l = threadIdx.x & 31;
    int beg = g_off[n], end = g_off[n + 1];
    float a0 = 0.f, a1 = 0.f;

    if (beg < end) {
        float mx = -INFINITY;
        for (int p = beg + l; p < end; p += 32) mx = fmaxf(mx, g_logits[p]);
#pragma unroll
        for (int o = 16; o; o >>= 1) mx = fmaxf(mx, __shfl_xor_sync(0xffffffffu, mx, o));

        float s = 0.f;
        for (int p = beg + l; p < end; p += 32) s += __expf(g_logits[p] - mx);
#pragma unroll
        for (int o = 16; o; o >>= 1) s += __shfl_xor_sync(0xffffffffu, s, o);
        float inv = 1.0f / s;

        for (int p = beg + l; p < end; p += 32)
            g_attp[p] = __expf(g_logits[p] - mx) * inv;

        for (int p = beg; p < end; p++) {
            float att = __expf(g_logits[p] - mx) * inv;   // broadcast L1 hit
            float2 xf = __half22float2(((const __half2*)(g_embh + (size_t)g_edge[p].x * DD))[l]);
            a0 += att * xf.x;
            a1 += att * xf.y;
        }
    }
    *(float2*)&g_hn0[(size_t)n * DD + 2 * l] = make_float2(a0, a1);
}

// ---------------- layer-1 gather (fp16 x1 copy, aligned 128B rows) --------
__global__ void k_gather1() {
    int n = blockIdx.x * 8 + (threadIdx.x >> 5);
    if (n >= N_ENT) return;
    int l = threadIdx.x & 31;
    int beg = g_off[n], end = g_off[n + 1];
    float a0 = 0.f, a1 = 0.f;
    for (int p = beg; p < end; p++) {
        float att = g_attp[p];
        float2 xf = __half22float2(((const __half2*)(g_x1h + (size_t)g_edge[p].x * DD))[l]);
        a0 += att * xf.x;
        a1 += att * xf.y;
    }
    *(float2*)&g_hn1[(size_t)n * DD + 2 * l] = make_float2(a0, a1);
}

// ---------------- layer 0 MLP via tf32 mma.sync (writes fp16 x1 too) ------
__global__ void k_mlp0mma(const float* __restrict__ x0,
                          const float* __restrict__ b1, const float* __restrict__ b2,
                          float* __restrict__ out) {
    extern __shared__ float dsm[];
    float* smAdd = dsm;
    float* smMul = dsm + 128 * PITCH;
    float* smW1  = dsm + 2 * 128 * PITCH;
    float* smW2  = smW1 + 64 * PITCH;
    const int tid = threadIdx.x;
    const int wid = tid >> 5, lane = tid & 31;
    const int g = lane >> 2, t4 = lane & 3;
    const int n0 = blockIdx.x * TILE_M;

    for (int idx = tid; idx < TILE_M * 16; idx += 256) {
        int m = idx >> 4, c = idx & 15;
        int n = n0 + m;
        float4 xv = make_float4(0.f, 0.f, 0.f, 0.f), hv = xv;
        if (n < N_ENT) {
            xv = ((const float4*)(x0 + (size_t)n * DD))[c];
            hv = ((const float4*)(g_hn0 + (size_t)n * DD))[c];
            ((float4*)(out + (size_t)n * OUTD))[c] = xv;
        }
        int k0 = c * 4;
        int base = m * PITCH + (k0 >> 3) * 8 + ((k0 & 7) >> 2);
        smAdd[base]     = to_tf32(xv.x + hv.x);
        smAdd[base + 2] = to_tf32(xv.y + hv.y);
        smAdd[base + 4] = to_tf32(xv.z + hv.z);
        smAdd[base + 6] = to_tf32(xv.w + hv.w);
        smMul[base]     = to_tf32(xv.x * hv.x);
        smMul[base + 2] = to_tf32(xv.y * hv.y);
        smMul[base + 4] = to_tf32(xv.z * hv.z);
        smMul[base + 6] = to_tf32(xv.w * hv.w);
    }
    for (int q = tid; q < 64 * 16; q += 256) {
        int row = q >> 4, c = q & 15;
        *(float4*)&smW1[row * PITCH + c * 4] = ((const float4*)(g_Wm + row * 64))[c];
        *(float4*)&smW2[row * PITCH + c * 4] = ((const float4*)(g_Wm + 4096 + row * 64))[c];
    }
    __syncthreads();

    const int mb = wid * 16;
    const int row0 = n0 + mb + g;
    const int row1 = row0 + 8;

    float acc_a[8][4], acc_m[8][4];
#pragma unroll
    for (int nt = 0; nt < 8; nt++)
#pragma unroll
        for (int q = 0; q < 4; q++) { acc_a[nt][q] = 0.f; acc_m[nt][q] = 0.f; }

#pragma unroll
    for (int ks = 0; ks < 8; ks++) {
        float2 pa0 = *(const float2*)&smAdd[(mb + g)     * PITCH + ks * 8 + t4 * 2];
        float2 pa1 = *(const float2*)&smAdd[(mb + g + 8) * PITCH + ks * 8 + t4 * 2];
        float2 pm0 = *(const float2*)&smMul[(mb + g)     * PITCH + ks * 8 + t4 * 2];
        float2 pm1 = *(const float2*)&smMul[(mb + g + 8) * PITCH + ks * 8 + t4 * 2];
        uint32_t aa0 = __float_as_uint(pa0.x), aa1 = __float_as_uint(pa1.x);
        uint32_t aa2 = __float_as_uint(pa0.y), aa3 = __float_as_uint(pa1.y);
        uint32_t am0 = __float_as_uint(pm0.x), am1 = __float_as_uint(pm1.x);
        uint32_t am2 = __float_as_uint(pm0.y), am3 = __float_as_uint(pm1.y);
#pragma unroll
        for (int nt = 0; nt < 8; nt++) {
            float2 pb1 = *(const float2*)&smW1[(nt * 8 + g) * PITCH + ks * 8 + t4 * 2];
            float2 pb2 = *(const float2*)&smW2[(nt * 8 + g) * PITCH + ks * 8 + t4 * 2];
            mma_tf32(acc_a[nt], aa0, aa1, aa2, aa3,
                     __float_as_uint(pb1.x), __float_as_uint(pb1.y));
            mma_tf32(acc_m[nt], am0, am1, am2, am3,
                     __float_as_uint(pb2.x), __float_as_uint(pb2.y));
        }
    }

#pragma unroll
    for (int nt = 0; nt < 8; nt++) {
        int j = nt * 8 + t4 * 2;
        float2 bb1 = *(const float2*)&b1[j];
        float2 bb2 = *(const float2*)&b2[j];
        if (row0 < N_ENT) {
            float2 y;
            y.x = leaky(acc_a[nt][0] + bb1.x) + leaky(acc_m[nt][0] + bb2.x);
            y.y = leaky(acc_a[nt][1] + bb1.y) + leaky(acc_m[nt][1] + bb2.y);
            *(float2*)&out[(size_t)row0 * OUTD + 64 + j] = y;
            ((__half2*)(g_x1h + (size_t)row0 * DD))[nt * 4 + t4] = __floats2half2_rn(y.x, y.y);
        }
        if (row1 < N_ENT) {
            float2 y;
            y.x = leaky(acc_a[nt][2] + bb1.x) + leaky(acc_m[nt][2] + bb2.x);
            y.y = leaky(acc_a[nt][3] + bb1.y) + leaky(acc_m[nt][3] + bb2.y);
            *(float2*)&out[(size_t)row1 * OUTD + 64 + j] = y;
            ((__half2*)(g_x1h + (size_t)row1 * DD))[nt * 4 + t4] = __floats2half2_rn(y.x, y.y);
        }
    }
}

// ---------------- layer 1 MLP (out dim 32, FFMA) ----------------
__global__ void k_mlp1(const float* __restrict__ W1, const float* __restrict__ b1,
                       const float* __restrict__ W2, const float* __restrict__ b2,
                       float* __restrict__ out) {
    extern __shared__ float dsm[];
    float* W1s = dsm;
    float* W2s = dsm + 64 * 36;
    float* sa  = dsm + 2 * 64 * 36;
    float* sm_ = dsm + 2 * 64 * 36 + 64 * 68;
    const int tid = threadIdx.x;

    for (int idx = tid; idx < 32 * DD; idx += 256) {
        int j = idx >> 6, d = idx & 63;
        W1s[d * 36 + j] = W1[idx];
        W2s[d * 36 + j] = W2[idx];
    }
    __syncthreads();

    const int jg = tid & 7, vgp = tid >> 3;
    const int j0 = jg * 4;
    const float4 b1v = *(const float4*)&b1[j0];
    const float4 b2v = *(const float4*)&b2[j0];
    const int NT = (N_ENT + 63) / 64;

    for (int t = blockIdx.x; t < NT; t += gridDim.x) {
        int n0 = t * 64;
        for (int q = tid; q < 64 * 16; q += 256) {
            int v = q >> 4, c = q & 15;
            int n = n0 + v;
            float4 xv = make_float4(0.f, 0.f, 0.f, 0.f), hv = xv;
            if (n < N_ENT) {
                xv = ((const float4*)(out + (size_t)n * OUTD + 64))[c];
                hv = ((const float4*)(g_hn1 + (size_t)n * DD))[c];
            }
            *(float4*)&sa [v * 68 + c * 4] = make_float4(xv.x + hv.x, xv.y + hv.y, xv.z + hv.z, xv.w + hv.w);
            *(float4*)&sm_[v * 68 + c * 4] = make_float4(xv.x * hv.x, xv.y * hv.y, xv.z * hv.z, xv.w * hv.w);
        }
        __syncthreads();

        float4 acc_a[2] = {}, acc_m[2] = {};
#pragma unroll
        for (int d4 = 0; d4 < 16; d4++) {
            float4 ea[2], em[2];
#pragma unroll
            for (int vv = 0; vv < 2; vv++) {
                ea[vv] = *(const float4*)&sa [(vgp * 2 + vv) * 68 + d4 * 4];
                em[vv] = *(const float4*)&sm_[(vgp * 2 + vv) * 68 + d4 * 4];
            }
#pragma unroll
            for (int dd = 0; dd < 4; dd++) {
                float4 w1 = *(const float4*)&W1s[(d4 * 4 + dd) * 36 + j0];
                float4 w2 = *(const float4*)&W2s[(d4 * 4 + dd) * 36 + j0];
#pragma unroll
                for (int vv = 0; vv < 2; vv++) {
                    float sA = dd == 0 ? ea[vv].x : dd == 1 ? ea[vv].y : dd == 2 ? ea[vv].z : ea[vv].w;
                    float sM = dd == 0 ? em[vv].x : dd == 1 ? em[vv].y : dd == 2 ? em[vv].z : em[vv].w;
                    fma4(acc_a[vv], sA, w1);
                    fma4(acc_m[vv], sM, w2);
                }
            }
        }
#pragma unroll
        for (int vv = 0; vv < 2; vv++) {
            int n = n0 + vgp * 2 + vv;
            if (n < N_ENT) {
                float4 r;
                r.x = leaky(acc_a[vv].x + b1v.x) + leaky(acc_m[vv].x + b2v.x);
                r.y = leaky(acc_a[vv].y + b1v.y) + leaky(acc_m[vv].y + b2v.y);
                r.z = leaky(acc_a[vv].z + b1v.z) + leaky(acc_m[vv].z + b2v.z);
                r.w = leaky(acc_a[vv].w + b1v.w) + leaky(acc_m[vv].w + b2v.w);
                *(float4*)&out[(size_t)n * OUTD + 128 + j0] = r;
            }
        }
        __syncthreads();
    }
}

// ---------------- launch ----------------
extern "C" void kernel_launch(void* const* d_in, const int* in_sizes, int n_in,
                              void* d_out, int out_size) {
    const float* entity_emb = (const float*)d_in[0];
    const float* rel_emb    = (const float*)d_in[1];
    const float* W_r        = (const float*)d_in[2];
    const float* W1_0_w     = (const float*)d_in[3];
    const float* W1_0_b     = (const float*)d_in[4];
    const float* W2_0_w     = (const float*)d_in[5];
    const float* W2_0_b     = (const float*)d_in[6];
    const float* W1_1_w     = (const float*)d_in[7];
    const float* W1_1_b     = (const float*)d_in[8];
    const float* W2_1_w     = (const float*)d_in[9];
    const float* W2_1_b     = (const float*)d_in[10];
    const int*   src        = (const int*)d_in[11];
    const int*   dst        = (const int*)d_in[12];
    const int*   et         = (const int*)d_in[13];
    float* out = (float*)d_out;

    const int SM_PROJ  = 128 * AP * 2;                           // 20480 B (A only)
    const int SM_MLP0  = (2 * 128 * PITCH + 2 * 64 * PITCH) * 4; // 110592 B
    const int SM_MLP1  = (2 * 64 * 36 + 2 * 64 * 68) * 4;        // 53248 B
    cudaFuncSetAttribute(k_projmma, cudaFuncAttributeMaxDynamicSharedMemorySize, SM_PROJ);
    cudaFuncSetAttribute(k_mlp0mma, cudaFuncAttributeMaxDynamicSharedMemorySize, SM_MLP0);
    cudaFuncSetAttribute(k_mlp1, cudaFuncAttributeMaxDynamicSharedMemorySize, SM_MLP1);

    // Fork a side stream off the capture stream (CSR build + preps run
    // concurrently with prepW -> projmma). Handles deliberately not destroyed.
    cudaStream_t s1;
    cudaStreamCreate(&s1);
    cudaEvent_t evF, evJ;
    cudaEventCreateWithFlags(&evF, cudaEventDisableTiming);
    cudaEventCreateWithFlags(&evJ, cudaEventDisableTiming);

    cudaEventRecord(evF, 0);
    cudaStreamWaitEvent(s1, evF, 0);

    // k_projmma stays kernel call #4 (ncu capture slot) to verify the delta.
    k_prepW<<<(N_REL * DD * DD + 255) / 256, 256>>>(W_r);          // 1 (main)
    k_init <<<(N_ENT + 255) / 256, 256, 0, s1>>>();                // 2 (s1)
    k_hist <<<(NE + 255) / 256, 256, 0, s1>>>(dst);                // 3 (s1)
    k_projmma<<<NTILES_M, 256, SM_PROJ>>>(entity_emb);             // 4 (main)
    k_scan1<<<NSCAN, 1024, 0, s1>>>();                             // 5 (s1)
    k_scan2<<<1, 128, 0, s1>>>();                                  // 6 (s1)
    k_scan3<<<(N_ENT + 255) / 256, 256, 0, s1>>>();                // 7 (s1)
    k_fill <<<(NE + 255) / 256, 256, 0, s1>>>(src, dst, et);       // 8 (s1)
    k_embh <<<(N_ENT * DD / 2 + 255) / 256, 256, 0, s1>>>(entity_emb);
    k_prepWm<<<(2 * DD * DD + 255) / 256, 256, 0, s1>>>(W1_0_w, W2_0_w);

    // join: logits needs g_proj (main) + g_edge (side)
    cudaEventRecord(evJ, s1);
    cudaStreamWaitEvent(0, evJ, 0);

    // edge-parallel logits (2 edges/warp); fused softmax + gather0; MLP0
    k_logits<<<(NE / 2 + 7) / 8, 256>>>(rel_emb);
    k_attgather<<<(N_ENT + 7) / 8, 256>>>();
    k_mlp0mma<<<NTILES_M, 256, SM_MLP0>>>(entity_emb, W1_0_b, W2_0_b, out);

    // layer 1
    k_gather1<<<(N_ENT + 7) / 8, 256>>>();
    k_mlp1<<<512, 256, SM_MLP1>>>(W1_1_w, W1_1_b, W2_1_w, W2_1_b, out);
}

// round 14
// speedup vs baseline: 1.1722x; 1.1722x over previous
#include <cuda_runtime.h>
#include <cuda_fp16.h>
#include <math.h>
#include <stdint.h>

#define N_ENT 100000
#define N_REL 12
#define DD 64
#define NE 1000000
#define OUTD 160   // 64 + 64 + 32
#define NSCAN ((N_ENT + 1023) / 1024)   // 98
#define TILE_M 128
#define NTILES_M ((N_ENT + TILE_M - 1) / TILE_M)   // 782
#define PITCH 72   // fp32 smem pitch (mlp0/mlp1): conflict-free fragment LDS.64
#define AP 80      // fp16 smem pitch: 40 words == 8 mod 32 -> conflict-free LDS.64

// ---------------- device scratch (no allocations allowed) ----------------
__device__ __half g_proj[(size_t)N_ENT * N_REL * DD];  // 153.6 MB (fp16)
__device__ __half g_embh[(size_t)N_ENT * DD];          // fp16 emb copy
__device__ __half g_x1h[(size_t)N_ENT * DD];           // fp16 x1 copy (aligned)
__device__ __half g_Wth[N_REL * DD * DD];  // W_r^T fp16, fragment-permuted (perm16)
__device__ float g_Wm[2 * DD * DD];        // W1_0^T, W2_0^T permuted tf32
__device__ float g_Wm1[2 * 32 * DD];       // W1_1^T, W2_1^T permuted tf32
__device__ float g_logits[NE];             // logits in CSR (dst-sorted) order
__device__ float g_attp[NE];               // att in CSR order
__device__ int4  g_edge[NE];               // CSR slot -> (src, etype, dst, _)
__device__ int   g_cnt[N_ENT];
__device__ int   g_off[N_ENT + 1];
__device__ int   g_cursor[N_ENT];
__device__ int   g_bsum[NSCAN];
__device__ float g_hn0[(size_t)N_ENT * DD];
__device__ float g_hn1[(size_t)N_ENT * DD];

// ---------------- helpers ----------------
__device__ __forceinline__ float leaky(float x) { return x > 0.0f ? x : 0.01f * x; }
__device__ __forceinline__ float to_tf32(float v) {
    float r;
    asm("cvt.rna.tf32.f32 %0, %1;" : "=f"(r) : "f"(v));
    return r;
}
__device__ __forceinline__ float ftanh(float x) {
    x = fminf(fmaxf(x, -20.f), 20.f);
    float e = __expf(2.f * x);
    return (e - 1.f) / (e + 1.f);
}
// perm16: m16n8k16 fragment halves {2t4,2t4+1,8+2t4,8+2t4+1} -> 4 contiguous
__device__ __forceinline__ int perm16(int k) {
    return (k & ~15) + (((k & 7) >> 1) << 2) + (((k & 8) >> 3) << 1) + (k & 1);
}
// m16n8k8 tf32 (mlp0/mlp1)
__device__ __forceinline__ void mma_tf32(float c[4], uint32_t a0, uint32_t a1,
                                         uint32_t a2, uint32_t a3,
                                         uint32_t b0, uint32_t b1) {
    asm volatile(
        "mma.sync.aligned.m16n8k8.row.col.f32.tf32.tf32.f32 "
        "{%0,%1,%2,%3}, {%4,%5,%6,%7}, {%8,%9}, {%0,%1,%2,%3};"
        : "+f"(c[0]), "+f"(c[1]), "+f"(c[2]), "+f"(c[3])
        : "r"(a0), "r"(a1), "r"(a2), "r"(a3), "r"(b0), "r"(b1));
}
// m16n8k16 fp16 in, fp32 accumulate (proj)
__device__ __forceinline__ void mma_f16(float c[4], uint32_t a0, uint32_t a1,
                                        uint32_t a2, uint32_t a3,
                                        uint32_t b0, uint32_t b1) {
    asm volatile(
        "mma.sync.aligned.m16n8k16.row.col.f32.f16.f16.f32 "
        "{%0,%1,%2,%3}, {%4,%5,%6,%7}, {%8,%9}, {%0,%1,%2,%3};"
        : "+f"(c[0]), "+f"(c[1]), "+f"(c[2]), "+f"(c[3])
        : "r"(a0), "r"(a1), "r"(a2), "r"(a3), "r"(b0), "r"(b1));
}

// ---------------- CSR build ----------------
__global__ void k_init() {
    int i = blockIdx.x * blockDim.x + threadIdx.x;
    if (i < N_ENT) g_cnt[i] = 0;
}

__global__ void k_hist(const int* __restrict__ dst) {
    int e = blockIdx.x * 256 + threadIdx.x;
    if (e < NE) atomicAdd(&g_cnt[dst[e]], 1);
}

__global__ void k_scan1() {
    __shared__ int s[1024];
    int i = blockIdx.x * 1024 + threadIdx.x;
    int v = (i < N_ENT) ? g_cnt[i] : 0;
    s[threadIdx.x] = v;
    __syncthreads();
    for (int off = 1; off < 1024; off <<= 1) {
        int t = (threadIdx.x >= off) ? s[threadIdx.x - off] : 0;
        __syncthreads();
        s[threadIdx.x] += t;
        __syncthreads();
    }
    if (i < N_ENT) g_off[i] = s[threadIdx.x] - v;
    if (threadIdx.x == 1023) g_bsum[blockIdx.x] = s[1023];
}

__global__ void k_scan2() {
    __shared__ int s[128];
    int t = threadIdx.x;
    int v0 = (t < NSCAN) ? g_bsum[t] : 0;
    s[t] = v0;
    __syncthreads();
    for (int off = 1; off < 128; off <<= 1) {
        int v = (t >= off) ? s[t - off] : 0;
        __syncthreads();
        s[t] += v;
        __syncthreads();
    }
    if (t < NSCAN) g_bsum[t] = s[t] - v0;   // exclusive
}

__global__ void k_scan3() {
    int i = blockIdx.x * 256 + threadIdx.x;
    if (i < N_ENT) {
        int o = g_off[i] + g_bsum[i >> 10];
        g_off[i] = o;
        g_cursor[i] = o;
    }
    if (i == 0) g_off[N_ENT] = NE;
}

__global__ void k_fill(const int* __restrict__ src, const int* __restrict__ dst,
                       const int* __restrict__ et) {
    int e = blockIdx.x * 256 + threadIdx.x;
    if (e < NE) {
        int d = dst[e];
        int pos = atomicAdd(&g_cursor[d], 1);
        g_edge[pos] = make_int4(src[e], et[e], d, 0);
    }
}

// ---------------- preps ----------------
__global__ void k_prepW(const float* __restrict__ Wr) {
    int idx = blockIdx.x * 256 + threadIdx.x;
    if (idx >= N_REL * DD * DD) return;
    int r = idx >> 12;
    int e = idx & 4095;
    int d = e >> 6, j = e & 63;
    g_Wth[r * 4096 + j * DD + perm16(d)] = __float2half(Wr[idx]);
}

__global__ void k_prepWm(const float* __restrict__ W1, const float* __restrict__ W2) {
    int idx = blockIdx.x * 256 + threadIdx.x;
    if (idx >= 2 * DD * DD) return;
    const float* srcw = (idx < 4096) ? W1 : W2;
    int e = idx & 4095;
    int j = e >> 6, d = e & 63;
    int pd = (d >> 3) * 8 + (d & 3) * 2 + ((d & 7) >> 2);
    g_Wm[(idx >> 12) * 4096 + j * DD + pd] = to_tf32(srcw[e]);
}

__global__ void k_prepWm1(const float* __restrict__ W1, const float* __restrict__ W2) {
    int idx = blockIdx.x * 256 + threadIdx.x;
    if (idx >= 2 * 32 * DD) return;
    const float* srcw = (idx < 2048) ? W1 : W2;
    int e = idx & 2047;
    int j = e >> 6, d = e & 63;
    int pd = (d >> 3) * 8 + (d & 3) * 2 + ((d & 7) >> 2);
    g_Wm1[(idx >> 11) * 2048 + j * DD + pd] = to_tf32(srcw[e]);
}

__global__ void k_embh(const float* __restrict__ emb) {
    int i = blockIdx.x * 256 + threadIdx.x;
    if (i < N_ENT * DD / 2) {
        float2 v = ((const float2*)emb)[i];
        ((__half2*)g_embh)[i] = __floats2half2_rn(v.x, v.y);
    }
}

// ---------------- fp16 m16n8k16 proj (R12-validated version) --------------
// smem: A[128][AP] halves, W[64][AP] halves. 30.7 KB total. 89us measured.
__global__ void k_projmma(const float* __restrict__ emb) {
    extern __shared__ char dsmc[];
    __half* smA = (__half*)dsmc;             // [128][AP]
    __half* smW = smA + 128 * AP;            // [64][AP]
    const int tid = threadIdx.x;
    const int wid = tid >> 5, lane = tid & 31;
    const int g = lane >> 2, t4 = lane & 3;
    const int n0 = blockIdx.x * TILE_M;

    for (int idx = tid; idx < TILE_M * 16; idx += 256) {
        int m = idx >> 4, c = idx & 15;
        float4 v = make_float4(0.f, 0.f, 0.f, 0.f);
        if (n0 + m < N_ENT) v = ((const float4*)(emb + (size_t)(n0 + m) * DD))[c];
        int k0 = c * 4;
        *(__half2*)&smA[m * AP + perm16(k0)]     = __floats2half2_rn(v.x, v.y);
        *(__half2*)&smA[m * AP + perm16(k0 + 2)] = __floats2half2_rn(v.z, v.w);
    }
    __syncthreads();

    const int mb = wid * 16;
    const int row0 = n0 + mb + g;
    const int row1 = row0 + 8;

    uint32_t af[4][4];
#pragma unroll
    for (int ks = 0; ks < 4; ks++) {
        uint2 ra = *(const uint2*)&smA[(mb + g)     * AP + ks * 16 + t4 * 4];
        uint2 rb = *(const uint2*)&smA[(mb + g + 8) * AP + ks * 16 + t4 * 4];
        af[ks][0] = ra.x;
        af[ks][1] = rb.x;
        af[ks][2] = ra.y;
        af[ks][3] = rb.y;
    }

    for (int r = 0; r < N_REL; r++) {
        for (int q = tid; q < 64 * 8; q += 256) {
            int row = q >> 3, ch = q & 7;
            *(float4*)&smW[row * AP + ch * 8] =
                ((const float4*)(g_Wth + r * 4096 + row * 64))[ch];
        }
        __syncthreads();

        float acc[8][4];
#pragma unroll
        for (int nt = 0; nt < 8; nt++)
#pragma unroll
            for (int q = 0; q < 4; q++) acc[nt][q] = 0.f;

#pragma unroll
        for (int ks = 0; ks < 4; ks++) {
#pragma unroll
            for (int nt = 0; nt < 8; nt++) {
                uint2 b = *(const uint2*)&smW[(nt * 8 + g) * AP + ks * 16 + t4 * 4];
                mma_f16(acc[nt], af[ks][0], af[ks][1], af[ks][2], af[ks][3],
                        b.x, b.y);
            }
        }

        if (row0 < N_ENT) {
            __half2* base = (__half2*)(g_proj + ((size_t)row0 * N_REL + r) * DD);
#pragma unroll
            for (int nt = 0; nt < 8; nt++)
                base[nt * 4 + t4] = __floats2half2_rn(acc[nt][0], acc[nt][1]);
        }
        if (row1 < N_ENT) {
            __half2* base = (__half2*)(g_proj + ((size_t)row1 * N_REL + r) * DD);
#pragma unroll
            for (int nt = 0; nt < 8; nt++)
                base[nt * 4 + t4] = __floats2half2_rn(acc[nt][2], acc[nt][3]);
        }
        __syncthreads();
    }
}

// ---------------- per-edge logits, 4 edges per warp (MLP=4) --------------
__global__ void k_logits(const float* __restrict__ rel_emb) {
    int q = blockIdx.x * 8 + (threadIdx.x >> 5);
    int p0 = q * 4;
    if (p0 >= NE) return;
    int l = threadIdx.x & 31;
    int4 e0 = g_edge[p0], e1 = g_edge[p0 + 1];
    int4 e2 = g_edge[p0 + 2], e3 = g_edge[p0 + 3];

    // 8 random row loads issued back-to-back (MLP=8 per lane)
    __half2 t0 = ((const __half2*)(g_proj + ((size_t)e0.x * N_REL + e0.y) * DD))[l];
    __half2 t1 = ((const __half2*)(g_proj + ((size_t)e1.x * N_REL + e1.y) * DD))[l];
    __half2 t2 = ((const __half2*)(g_proj + ((size_t)e2.x * N_REL + e2.y) * DD))[l];
    __half2 t3 = ((const __half2*)(g_proj + ((size_t)e3.x * N_REL + e3.y) * DD))[l];
    __half2 h0 = ((const __half2*)(g_proj + ((size_t)e0.z * N_REL + e0.y) * DD))[l];
    __half2 h1 = ((const __half2*)(g_proj + ((size_t)e1.z * N_REL + e1.y) * DD))[l];
    __half2 h2 = ((const __half2*)(g_proj + ((size_t)e2.z * N_REL + e2.y) * DD))[l];
    __half2 h3 = ((const __half2*)(g_proj + ((size_t)e3.z * N_REL + e3.y) * DD))[l];
    float2 r0 = ((const float2*)(rel_emb + (size_t)e0.y * DD))[l];
    float2 r1 = ((const float2*)(rel_emb + (size_t)e1.y * DD))[l];
    float2 r2 = ((const float2*)(rel_emb + (size_t)e2.y * DD))[l];
    float2 r3 = ((const float2*)(rel_emb + (size_t)e3.y * DD))[l];

    float2 tv0 = __half22float2(t0), hv0 = __half22float2(h0);
    float2 tv1 = __half22float2(t1), hv1 = __half22float2(h1);
    float2 tv2 = __half22float2(t2), hv2 = __half22float2(h2);
    float2 tv3 = __half22float2(t3), hv3 = __half22float2(h3);

    float s0 = tv0.x * ftanh(hv0.x + r0.x) + tv0.y * ftanh(hv0.y + r0.y);
    float s1 = tv1.x * ftanh(hv1.x + r1.x) + tv1.y * ftanh(hv1.y + r1.y);
    float s2 = tv2.x * ftanh(hv2.x + r2.x) + tv2.y * ftanh(hv2.y + r2.y);
    float s3 = tv3.x * ftanh(hv3.x + r3.x) + tv3.y * ftanh(hv3.y + r3.y);
#pragma unroll
    for (int o = 16; o; o >>= 1) {
        s0 += __shfl_xor_sync(0xffffffffu, s0, o);
        s1 += __shfl_xor_sync(0xffffffffu, s1, o);
        s2 += __shfl_xor_sync(0xffffffffu, s2, o);
        s3 += __shfl_xor_sync(0xffffffffu, s3, o);
    }
    if (l == 0) *(float4*)&g_logits[p0] = make_float4(s0, s1, s2, s3);
}

// ---------------- fused softmax + layer-0 gather (warp per node) ----------
__global__ void k_attgather() {
    int n = blockIdx.x * 8 + (threadIdx.x >> 5);
    if (n >= N_ENT) return;
    int l = threadIdx.x & 31;
    int beg = g_off[n], end = g_off[n + 1];
    float a0 = 0.f, a1 = 0.f;

    if (beg < end) {
        float mx = -INFINITY;
        for (int p = beg + l; p < end; p += 32) mx = fmaxf(mx, g_logits[p]);
#pragma unroll
        for (int o = 16; o; o >>= 1) mx = fmaxf(mx, __shfl_xor_sync(0xffffffffu, mx, o));

        float s = 0.f;
        for (int p = beg + l; p < end; p += 32) s += __expf(g_logits[p] - mx);
#pragma unroll
        for (int o = 16; o; o >>= 1) s += __shfl_xor_sync(0xffffffffu, s, o);
        float inv = 1.0f / s;

        for (int p = beg + l; p < end; p += 32)
            g_attp[p] = __expf(g_logits[p] - mx) * inv;

        for (int p = beg; p < end; p++) {
            float att = __expf(g_logits[p] - mx) * inv;   // broadcast L1 hit
            float2 xf = __half22float2(((const __half2*)(g_embh + (size_t)g_edge[p].x * DD))[l]);
            a0 += att * xf.x;
            a1 += att * xf.y;
        }
    }
    *(float2*)&g_hn0[(size_t)n * DD + 2 * l] = make_float2(a0, a1);
}

// ---------------- layer-1 gather (fp16 x1 copy, aligned 128B rows) --------
__global__ void k_gather1() {
    int n = blockIdx.x * 8 + (threadIdx.x >> 5);
    if (n >= N_ENT) return;
    int l = threadIdx.x & 31;
    int beg = g_off[n], end = g_off[n + 1];
    float a0 = 0.f, a1 = 0.f;
    for (int p = beg; p < end; p++) {
        float att = g_attp[p];
        float2 xf = __half22float2(((const __half2*)(g_x1h + (size_t)g_edge[p].x * DD))[l]);
        a0 += att * xf.x;
        a1 += att * xf.y;
    }
    *(float2*)&g_hn1[(size_t)n * DD + 2 * l] = make_float2(a0, a1);
}

// ---------------- layer 0 MLP via tf32 mma.sync (writes fp16 x1 too) ------
__global__ void k_mlp0mma(const float* __restrict__ x0,
                          const float* __restrict__ b1, const float* __restrict__ b2,
                          float* __restrict__ out) {
    extern __shared__ float dsm[];
    float* smAdd = dsm;
    float* smMul = dsm + 128 * PITCH;
    float* smW1  = dsm + 2 * 128 * PITCH;
    float* smW2  = smW1 + 64 * PITCH;
    const int tid = threadIdx.x;
    const int wid = tid >> 5, lane = tid & 31;
    const int g = lane >> 2, t4 = lane & 3;
    const int n0 = blockIdx.x * TILE_M;

    for (int idx = tid; idx < TILE_M * 16; idx += 256) {
        int m = idx >> 4, c = idx & 15;
        int n = n0 + m;
        float4 xv = make_float4(0.f, 0.f, 0.f, 0.f), hv = xv;
        if (n < N_ENT) {
            xv = ((const float4*)(x0 + (size_t)n * DD))[c];
            hv = ((const float4*)(g_hn0 + (size_t)n * DD))[c];
            ((float4*)(out + (size_t)n * OUTD))[c] = xv;
        }
        int k0 = c * 4;
        int base = m * PITCH + (k0 >> 3) * 8 + ((k0 & 7) >> 2);
        smAdd[base]     = to_tf32(xv.x + hv.x);
        smAdd[base + 2] = to_tf32(xv.y + hv.y);
        smAdd[base + 4] = to_tf32(xv.z + hv.z);
        smAdd[base + 6] = to_tf32(xv.w + hv.w);
        smMul[base]     = to_tf32(xv.x * hv.x);
        smMul[base + 2] = to_tf32(xv.y * hv.y);
        smMul[base + 4] = to_tf32(xv.z * hv.z);
        smMul[base + 6] = to_tf32(xv.w * hv.w);
    }
    for (int q = tid; q < 64 * 16; q += 256) {
        int row = q >> 4, c = q & 15;
        *(float4*)&smW1[row * PITCH + c * 4] = ((const float4*)(g_Wm + row * 64))[c];
        *(float4*)&smW2[row * PITCH + c * 4] = ((const float4*)(g_Wm + 4096 + row * 64))[c];
    }
    __syncthreads();

    const int mb = wid * 16;
    const int row0 = n0 + mb + g;
    const int row1 = row0 + 8;

    float acc_a[8][4], acc_m[8][4];
#pragma unroll
    for (int nt = 0; nt < 8; nt++)
#pragma unroll
        for (int q = 0; q < 4; q++) { acc_a[nt][q] = 0.f; acc_m[nt][q] = 0.f; }

#pragma unroll
    for (int ks = 0; ks < 8; ks++) {
        float2 pa0 = *(const float2*)&smAdd[(mb + g)     * PITCH + ks * 8 + t4 * 2];
        float2 pa1 = *(const float2*)&smAdd[(mb + g + 8) * PITCH + ks * 8 + t4 * 2];
        float2 pm0 = *(const float2*)&smMul[(mb + g)     * PITCH + ks * 8 + t4 * 2];
        float2 pm1 = *(const float2*)&smMul[(mb + g + 8) * PITCH + ks * 8 + t4 * 2];
        uint32_t aa0 = __float_as_uint(pa0.x), aa1 = __float_as_uint(pa1.x);
        uint32_t aa2 = __float_as_uint(pa0.y), aa3 = __float_as_uint(pa1.y);
        uint32_t am0 = __float_as_uint(pm0.x), am1 = __float_as_uint(pm1.x);
        uint32_t am2 = __float_as_uint(pm0.y), am3 = __float_as_uint(pm1.y);
#pragma unroll
        for (int nt = 0; nt < 8; nt++) {
            float2 pb1 = *(const float2*)&smW1[(nt * 8 + g) * PITCH + ks * 8 + t4 * 2];
            float2 pb2 = *(const float2*)&smW2[(nt * 8 + g) * PITCH + ks * 8 + t4 * 2];
            mma_tf32(acc_a[nt], aa0, aa1, aa2, aa3,
                     __float_as_uint(pb1.x), __float_as_uint(pb1.y));
            mma_tf32(acc_m[nt], am0, am1, am2, am3,
                     __float_as_uint(pb2.x), __float_as_uint(pb2.y));
        }
    }

#pragma unroll
    for (int nt = 0; nt < 8; nt++) {
        int j = nt * 8 + t4 * 2;
        float2 bb1 = *(const float2*)&b1[j];
        float2 bb2 = *(const float2*)&b2[j];
        if (row0 < N_ENT) {
            float2 y;
            y.x = leaky(acc_a[nt][0] + bb1.x) + leaky(acc_m[nt][0] + bb2.x);
            y.y = leaky(acc_a[nt][1] + bb1.y) + leaky(acc_m[nt][1] + bb2.y);
            *(float2*)&out[(size_t)row0 * OUTD + 64 + j] = y;
            ((__half2*)(g_x1h + (size_t)row0 * DD))[nt * 4 + t4] = __floats2half2_rn(y.x, y.y);
        }
        if (row1 < N_ENT) {
            float2 y;
            y.x = leaky(acc_a[nt][2] + bb1.x) + leaky(acc_m[nt][2] + bb2.x);
            y.y = leaky(acc_a[nt][3] + bb1.y) + leaky(acc_m[nt][3] + bb2.y);
            *(float2*)&out[(size_t)row1 * OUTD + 64 + j] = y;
            ((__half2*)(g_x1h + (size_t)row1 * DD))[nt * 4 + t4] = __floats2half2_rn(y.x, y.y);
        }
    }
}

// ---------------- layer 1 MLP via tf32 mma.sync (N=32 clone of mlp0) ------
__global__ void k_mlp1mma(const float* __restrict__ b1, const float* __restrict__ b2,
                          float* __restrict__ out) {
    extern __shared__ float dsm[];
    float* smAdd = dsm;                      // [128][PITCH]
    float* smMul = dsm + 128 * PITCH;
    float* smW1  = dsm + 2 * 128 * PITCH;    // [32][PITCH]
    float* smW2  = smW1 + 32 * PITCH;
    const int tid = threadIdx.x;
    const int wid = tid >> 5, lane = tid & 31;
    const int g = lane >> 2, t4 = lane & 3;
    const int n0 = blockIdx.x * TILE_M;

    for (int idx = tid; idx < TILE_M * 16; idx += 256) {
        int m = idx >> 4, c = idx & 15;
        int n = n0 + m;
        float4 xv = make_float4(0.f, 0.f, 0.f, 0.f), hv = xv;
        if (n < N_ENT) {
            xv = ((const float4*)(out + (size_t)n * OUTD + 64))[c];
            hv = ((const float4*)(g_hn1 + (size_t)n * DD))[c];
        }
        int k0 = c * 4;
        int base = m * PITCH + (k0 >> 3) * 8 + ((k0 & 7) >> 2);
        smAdd[base]     = to_tf32(xv.x + hv.x);
        smAdd[base + 2] = to_tf32(xv.y + hv.y);
        smAdd[base + 4] = to_tf32(xv.z + hv.z);
        smAdd[base + 6] = to_tf32(xv.w + hv.w);
        smMul[base]     = to_tf32(xv.x * hv.x);
        smMul[base + 2] = to_tf32(xv.y * hv.y);
        smMul[base + 4] = to_tf32(xv.z * hv.z);
        smMul[base + 6] = to_tf32(xv.w * hv.w);
    }
    for (int q = tid; q < 32 * 16; q += 256) {
        int row = q >> 4, c = q & 15;
        *(float4*)&smW1[row * PITCH + c * 4] = ((const float4*)(g_Wm1 + row * 64))[c];
        *(float4*)&smW2[row * PITCH + c * 4] = ((const float4*)(g_Wm1 + 2048 + row * 64))[c];
    }
    __syncthreads();

    const int mb = wid * 16;
    const int row0 = n0 + mb + g;
    const int row1 = row0 + 8;

    float acc_a[4][4], acc_m[4][4];
#pragma unroll
    for (int nt = 0; nt < 4; nt++)
#pragma unroll
        for (int q = 0; q < 4; q++) { acc_a[nt][q] = 0.f; acc_m[nt][q] = 0.f; }

#pragma unroll
    for (int ks = 0; ks < 8; ks++) {
        float2 pa0 = *(const float2*)&smAdd[(mb + g)     * PITCH + ks * 8 + t4 * 2];
        float2 pa1 = *(const float2*)&smAdd[(mb + g + 8) * PITCH + ks * 8 + t4 * 2];
        float2 pm0 = *(const float2*)&smMul[(mb + g)     * PITCH + ks * 8 + t4 * 2];
        float2 pm1 = *(const float2*)&smMul[(mb + g + 8) * PITCH + ks * 8 + t4 * 2];
        uint32_t aa0 = __float_as_uint(pa0.x), aa1 = __float_as_uint(pa1.x);
        uint32_t aa2 = __float_as_uint(pa0.y), aa3 = __float_as_uint(pa1.y);
        uint32_t am0 = __float_as_uint(pm0.x), am1 = __float_as_uint(pm1.x);
        uint32_t am2 = __float_as_uint(pm0.y), am3 = __float_as_uint(pm1.y);
#pragma unroll
        for (int nt = 0; nt < 4; nt++) {
            float2 pb1 = *(const float2*)&smW1[(nt * 8 + g) * PITCH + ks * 8 + t4 * 2];
            float2 pb2 = *(const float2*)&smW2[(nt * 8 + g) * PITCH + ks * 8 + t4 * 2];
            mma_tf32(acc_a[nt], aa0, aa1, aa2, aa3,
                     __float_as_uint(pb1.x), __float_as_uint(pb1.y));
            mma_tf32(acc_m[nt], am0, am1, am2, am3,
                     __float_as_uint(pb2.x), __float_as_uint(pb2.y));
        }
    }

#pragma unroll
    for (int nt = 0; nt < 4; nt++) {
        int j = nt * 8 + t4 * 2;
        float2 bb1 = *(const float2*)&b1[j];
        float2 bb2 = *(const float2*)&b2[j];
        if (row0 < N_ENT) {
            float2 y;
            y.x = leaky(acc_a[nt][0] + bb1.x) + leaky(acc_m[nt][0] + bb2.x);
            y.y = leaky(acc_a[nt][1] + bb1.y) + leaky(acc_m[nt][1] + bb2.y);
            *(float2*)&out[(size_t)row0 * OUTD + 128 + j] = y;
        }
        if (row1 < N_ENT) {
            float2 y;
            y.x = leaky(acc_a[nt][2] + bb1.x) + leaky(acc_m[nt][2] + bb2.x);
            y.y = leaky(acc_a[nt][3] + bb1.y) + leaky(acc_m[nt][3] + bb2.y);
            *(float2*)&out[(size_t)row1 * OUTD + 128 + j] = y;
        }
    }
}

// ---------------- launch ----------------
extern "C" void kernel_launch(void* const* d_in, const int* in_sizes, int n_in,
                              void* d_out, int out_size) {
    const float* entity_emb = (const float*)d_in[0];
    const float* rel_emb    = (const float*)d_in[1];
    const float* W_r        = (const float*)d_in[2];
    const float* W1_0_w     = (const float*)d_in[3];
    const float* W1_0_b     = (const float*)d_in[4];
    const float* W2_0_w     = (const float*)d_in[5];
    const float* W2_0_b     = (const float*)d_in[6];
    const float* W1_1_w     = (const float*)d_in[7];
    const float* W1_1_b     = (const float*)d_in[8];
    const float* W2_1_w     = (const float*)d_in[9];
    const float* W2_1_b     = (const float*)d_in[10];
    const int*   src        = (const int*)d_in[11];
    const int*   dst        = (const int*)d_in[12];
    const int*   et         = (const int*)d_in[13];
    float* out = (float*)d_out;

    const int SM_PROJ  = (128 * AP + 64 * AP) * 2;               // 30720 B
    const int SM_MLP0  = (2 * 128 * PITCH + 2 * 64 * PITCH) * 4; // 110592 B
    const int SM_MLP1  = (2 * 128 * PITCH + 2 * 32 * PITCH) * 4; // 92160 B
    cudaFuncSetAttribute(k_projmma, cudaFuncAttributeMaxDynamicSharedMemorySize, SM_PROJ);
    cudaFuncSetAttribute(k_mlp0mma, cudaFuncAttributeMaxDynamicSharedMemorySize, SM_MLP0);
    cudaFuncSetAttribute(k_mlp1mma, cudaFuncAttributeMaxDynamicSharedMemorySize, SM_MLP1);

    // Fork a side stream off the capture stream (CSR build + preps run
    // concurrently with prepW -> projmma). Handles deliberately not destroyed.
    cudaStream_t s1;
    cudaStreamCreate(&s1);
    cudaEvent_t evF, evJ;
    cudaEventCreateWithFlags(&evF, cudaEventDisableTiming);
    cudaEventCreateWithFlags(&evJ, cudaEventDisableTiming);

    cudaEventRecord(evF, 0);
    cudaStreamWaitEvent(s1, evF, 0);

    // k_projmma stays kernel call #4 (ncu capture slot) to verify the revert.
    k_prepW<<<(N_REL * DD * DD + 255) / 256, 256>>>(W_r);          // 1 (main)
    k_init <<<(N_ENT + 255) / 256, 256, 0, s1>>>();                // 2 (s1)
    k_hist <<<(NE + 255) / 256, 256, 0, s1>>>(dst);                // 3 (s1)
    k_projmma<<<NTILES_M, 256, SM_PROJ>>>(entity_emb);             // 4 (main)
    k_scan1<<<NSCAN, 1024, 0, s1>>>();                             // 5 (s1)
    k_scan2<<<1, 128, 0, s1>>>();                                  // 6 (s1)
    k_scan3<<<(N_ENT + 255) / 256, 256, 0, s1>>>();                // 7 (s1)
    k_fill <<<(NE + 255) / 256, 256, 0, s1>>>(src, dst, et);       // 8 (s1)
    k_embh <<<(N_ENT * DD / 2 + 255) / 256, 256, 0, s1>>>(entity_emb);
    k_prepWm<<<(2 * DD * DD + 255) / 256, 256, 0, s1>>>(W1_0_w, W2_0_w);
    k_prepWm1<<<(2 * 32 * DD + 255) / 256, 256, 0, s1>>>(W1_1_w, W2_1_w);

    // join: logits needs g_proj (main) + g_edge (side)
    cudaEventRecord(evJ, s1);
    cudaStreamWaitEvent(0, evJ, 0);

    // edge-parallel logits (4 edges/warp); fused softmax + gather0; MLP0
    k_logits<<<(NE / 4 + 7) / 8, 256>>>(rel_emb);
    k_attgather<<<(N_ENT + 7) / 8, 256>>>();
    k_mlp0mma<<<NTILES_M, 256, SM_MLP0>>>(entity_emb, W1_0_b, W2_0_b, out);

    // layer 1
    k_gather1<<<(N_ENT + 7) / 8, 256>>>();
    k_mlp1mma<<<NTILES_M, 256, SM_MLP1>>>(W1_1_b, W2_1_b, out);
}